// round 15
// baseline (speedup 1.0000x reference)
#include <cuda_runtime.h>
#include <cuda_fp16.h>
#include <math.h>

typedef unsigned long long u64;
typedef unsigned int u32;
typedef unsigned short u16;

// -------- prepped fragment-order weight streams (fp16 hi/lo, 2-term split) --------
__device__ __align__(128) unsigned char g_enc[393216];  // 12 chunks x 32KB, Ktilde=768
__device__ __align__(128) unsigned char g_ssm[327680];  // 10 chunks x 32KB, Ktilde=640
__device__ __align__(128) unsigned char g_cw[65536];    //  2 chunks x 32KB, Ktilde=512

__device__ __forceinline__ u16 hf_hi(float w) { return __half_as_ushort(__float2half_rn(w)); }
__device__ __forceinline__ u16 hf_lo(float w) {
    float h = __half2float(__float2half_rn(w));
    return __half_as_ushort(__float2half_rn(w - h));
}

// One thread per output fp16. Layout: chunk(32KB) -> slab(8KB enc/ssm, 2KB C) ->
// block(512B, (warp,mtile)) -> lane(16B) -> 4 regs x f16x2, matching the PTX
// m16n8k16 A-fragment: reg r holds (row + (r&1)*8, k + (r>>1)*8 + h).
__global__ void prep(const float* __restrict__ A_w, const float* __restrict__ B_w,
                     const float* __restrict__ C_w, const float* __restrict__ W_ih,
                     const float* __restrict__ W_hh) {
    u32 e = blockIdx.x * 256u + threadIdx.x;
    u32 kind, pos;
    if (e < 196608u)      { kind = 0; pos = e * 2u; }
    else if (e < 360448u) { kind = 1; pos = (e - 196608u) * 2u; }
    else if (e < 393216u) { kind = 2; pos = (e - 360448u) * 2u; }
    else return;
    u32 chunk = pos >> 15, inch = pos & 32767u;
    u32 slab, w, m, r3;
    if (kind < 2) { slab = inch >> 13; u32 r2 = inch & 8191u; u32 blk = r2 >> 9; w = blk >> 1; m = blk & 1u; r3 = r2 & 511u; }
    else          { slab = inch >> 11; u32 r2 = inch & 2047u; w = r2 >> 9; m = 0; r3 = r2 & 511u; }
    u32 t = r3 >> 4, r4 = r3 & 15u, reg = r4 >> 2, h = (r4 & 3u) >> 1;
    u32 row = (t >> 2) + (reg & 1u) * 8u;
    u32 kl  = (t & 3u) * 2u + (reg >> 1) * 8u + h;
    float src; u32 p;
    if (kind == 0) {
        u32 j = w * 32u + m * 16u + row;
        u32 kt = (chunk * 4u + slab) * 16u + kl;
        p = kt / 384u; u32 kk = kt % 384u;
        src = (kk < 128u) ? W_ih[j * 128u + kk] : W_hh[j * 256u + kk - 128u];
        *(u16*)(g_enc + pos) = p ? hf_lo(src) : hf_hi(src);
    } else if (kind == 1) {
        u32 j = w * 32u + m * 16u + row;
        u32 kt = (chunk * 4u + slab) * 16u + kl;
        p = kt / 320u; u32 kk = kt % 320u;
        src = (kk < 64u) ? B_w[j * 64u + kk] : A_w[j * 256u + kk - 64u];
        *(u16*)(g_ssm + pos) = p ? hf_lo(src) : hf_hi(src);
    } else {
        u32 o = w * 16u + row;
        u32 g4 = chunk * 16u + slab;
        p = g4 >> 4;
        u32 k = (g4 & 15u) * 16u + kl;        // 0..255
        src = C_w[o * 256u + k];
        *(u16*)(g_cw + pos) = p ? hf_lo(src) : hf_hi(src);
    }
}

// ---------------- PTX helpers ----------------
__device__ __forceinline__ u32 smem_u32(const void* p) {
    u32 a;
    asm("{ .reg .u64 t; cvta.to.shared.u64 t, %1; cvt.u32.u64 %0, t; }" : "=r"(a) : "l"(p));
    return a;
}
#define STS16(addr, v)  asm volatile("st.shared.u16 [%0], %1;" :: "r"(addr), "h"(v))
#define STS32(addr, f)  asm volatile("st.shared.f32 [%0], %1;" :: "r"(addr), "f"(f))
#define STSU32(addr, v) asm volatile("st.shared.u32 [%0], %1;" :: "r"(addr), "r"(v))
#define LDS32U(r, addr) asm volatile("ld.shared.u32 %0, [%1];" : "=r"(r) : "r"(addr))

#define MMA16816(c, a, b0, b1) \
    asm volatile("mma.sync.aligned.m16n8k16.row.col.f32.f16.f16.f32 " \
                 "{%0,%1,%2,%3},{%4,%5,%6,%7},{%8,%9},{%0,%1,%2,%3};" \
                 : "+f"((c)[0]), "+f"((c)[1]), "+f"((c)[2]), "+f"((c)[3]) \
                 : "r"((a)[0]), "r"((a)[1]), "r"((a)[2]), "r"((a)[3]), "r"(b0), "r"(b1))

__device__ __forceinline__ float my_tanh(float x) {
    float ax = fabsf(x);
    float e  = __expf(2.0f * ax);
    float r  = 1.0f - 2.0f / (e + 1.0f);
    return copysignf(r, x);
}

// ---------------- smem layout: U only (16 batch rows per CTA) ----------------
constexpr u32 UP = 1552;                 // U row pitch bytes (UP%128==16 -> conflict-free)
constexpr u32 SMEM_TOTAL = 16 * UP;      // 24832 per CTA (2 CTAs/SM -> ~50KB)

// dual-slot U write: hi at k, lo at k+P (Pb = part stride bytes)
__device__ __forceinline__ void put_duo(u32 ub, u32 k, float v, u32 Pb) {
    __half hb = __float2half_rn(v);
    u16 hi = __half_as_ushort(hb);
    u16 lo = __half_as_ushort(__float2half_rn(v - __half2float(hb)));
    u32 a = ub + k * 2u;
    STS16(a, hi); STS16(a + Pb, lo);
}

// stage 8/4 consecutive k-slots for one batch row: vector LDG + paired STS32
__device__ __forceinline__ void stage8(u32 ub, u32 k0, const float* s, u32 Pb) {
    float v[8];
    const float4* s4 = (const float4*)s;
#pragma unroll
    for (int q = 0; q < 2; q++) {
        float4 f = __ldg(s4 + q);
        v[q * 4] = f.x; v[q * 4 + 1] = f.y; v[q * 4 + 2] = f.z; v[q * 4 + 3] = f.w;
    }
#pragma unroll
    for (int i = 0; i < 8; i += 2) {
        __half a = __float2half_rn(v[i]), b = __float2half_rn(v[i + 1]);
        __half al = __float2half_rn(v[i] - __half2float(a));
        __half bl = __float2half_rn(v[i + 1] - __half2float(b));
        u32 hi = (u32)__half_as_ushort(a) | ((u32)__half_as_ushort(b) << 16);
        u32 lo = (u32)__half_as_ushort(al) | ((u32)__half_as_ushort(bl) << 16);
        u32 ad = ub + (k0 + (u32)i) * 2u;
        STSU32(ad, hi); STSU32(ad + Pb, lo);
    }
}
__device__ __forceinline__ void stage4(u32 ub, u32 k0, const float* s, u32 Pb) {
    float4 f = __ldg((const float4*)s);
    float v[4] = {f.x, f.y, f.z, f.w};
#pragma unroll
    for (int i = 0; i < 4; i += 2) {
        __half a = __float2half_rn(v[i]), b = __float2half_rn(v[i + 1]);
        __half al = __float2half_rn(v[i] - __half2float(a));
        __half bl = __float2half_rn(v[i + 1] - __half2float(b));
        u32 hi = (u32)__half_as_ushort(a) | ((u32)__half_as_ushort(b) << 16);
        u32 lo = (u32)__half_as_ushort(al) | ((u32)__half_as_ushort(bl) << 16);
        u32 ad = ub + (k0 + (u32)i) * 2u;
        STSU32(ad, hi); STSU32(ad + Pb, lo);
    }
}

// ---- half-chunk (2-slab) helpers; N=16 (2 n-tiles) keeps regs under 128 ----
__device__ __forceinline__ void half_load(uint4 (&A)[4], const uint4* __restrict__ ap,
                                          u32 half /* slab pair index */) {
    const uint4* p = ap + half * 1024u;   // 2 slabs * 8192B = 16384B = 1024 uint4
#pragma unroll
    for (int sl = 0; sl < 2; sl++) {
        A[sl * 2]     = __ldg(p + sl * 512);
        A[sl * 2 + 1] = __ldg(p + sl * 512 + 32);
    }
}
__device__ __forceinline__ void half_compute(const uint4 (&A)[4], u32 bB, u32 kt0,
                                             float acc[2][2][4]) {
#pragma unroll
    for (int sl = 0; sl < 2; sl++) {
        u32 bk = bB + (kt0 + (u32)sl * 16u) * 2u;
        u32 b0[2], b1[2];
#pragma unroll
        for (int nt = 0; nt < 2; nt++) {
            LDS32U(b0[nt], bk + (u32)nt * (8u * UP));
            LDS32U(b1[nt], bk + (u32)nt * (8u * UP) + 16u);
        }
        const u32* a0 = (const u32*)&A[sl * 2];
        const u32* a1 = (const u32*)&A[sl * 2 + 1];
#pragma unroll
        for (int nt = 0; nt < 2; nt++) {
            MMA16816(acc[0][nt], a0, b0[nt], b1[nt]);
            MMA16816(acc[1][nt], a1, b0[nt], b1[nt]);
        }
    }
}

// main GEMM over NH half-chunks (NH even): A half-chunk register ping-pong.
template <int NH>
__device__ __forceinline__ void gemm_g(const unsigned char* __restrict__ gw,
                                       u32 Ub, int warp, int lane,
                                       float acc[2][2][4]) {
    static_assert(NH % 2 == 0, "NH even");
    const u32 bB = Ub + (u32)(lane >> 2) * UP + (u32)(lane & 3) * 4u;
    const uint4* __restrict__ ap =
        (const uint4*)(gw + (u32)(warp * 1024) + (u32)(lane * 16));
    uint4 A0[4], A1[4];
    half_load(A0, ap, 0);
#pragma unroll 1
    for (int h = 0; h < NH; h += 2) {
        half_load(A1, ap, (u32)(h + 1));
        half_compute(A0, bB, (u32)h * 32u, acc);
        if (h + 2 < NH) half_load(A0, ap, (u32)(h + 2));
        half_compute(A1, bB, (u32)(h + 1) * 32u, acc);
    }
}

__global__ __launch_bounds__(256, 2) void ss_main(
    const float* __restrict__ pre_x, const float* __restrict__ pre_y,
    const float* __restrict__ fwd_x,
    const float* __restrict__ A_b, const float* __restrict__ B_b,
    const float* __restrict__ C_b, const float* __restrict__ b_ih,
    const float* __restrict__ b_hh, float* __restrict__ out)
{
    extern __shared__ char smraw[];
    const u32 SB = smem_u32(smraw);
    const int tid = threadIdx.x, lane = tid & 31, warp = tid >> 5;
    const int bbase = blockIdx.x * 16;
    const int gg = lane >> 2, tig = lane & 3;

    // zero U
    for (int i = tid; i < (int)(SMEM_TOTAL / 4); i += 256) STS32(SB + (u32)i * 4u, 0.0f);
    // stage x0,y0 (enc layout: x at k 0..63, y at 64..127; part stride 768B)
    {
        int b = tid >> 4, k8 = (tid & 15) * 8;
        const float* s = ((k8 < 64) ? pre_x : pre_y) + (size_t)(bbase + b) * 64 + (k8 & 63);
        stage8(SB + (u32)b * UP, (u32)k8, s, 768u);
    }

    // biases in regs
    float ebias[4], sbias[4], cb[2];
#pragma unroll
    for (int m = 0; m < 2; m++)
#pragma unroll
        for (int rh = 0; rh < 2; rh++) {
            int j = warp * 32 + m * 16 + gg + rh * 8;
            ebias[m * 2 + rh] = b_ih[j] + b_hh[j];
            sbias[m * 2 + rh] = A_b[j] + B_b[j];
        }
    cb[0] = C_b[(warp & 3) * 16 + gg];
    cb[1] = C_b[(warp & 3) * 16 + gg + 8];
    __syncthreads();

    // ================= encoder =================
    for (int t = 0; t < 64; t++) {
        float acc[2][2][4] = {};
        gemm_g<24>(g_enc, SB, warp, lane, acc);
        __syncthreads();                       // all reads of old U done
        const bool last = (t == 63);
        const u32 hb = last ? 64u : 128u;      // h base slot (ssm vs enc layout)
        const u32 Pb = last ? 640u : 768u;     // part stride bytes
#pragma unroll
        for (int m = 0; m < 2; m++)
#pragma unroll
            for (int nt = 0; nt < 2; nt++)
#pragma unroll
                for (int r = 0; r < 4; r++) {
                    int j = warp * 32 + m * 16 + gg + (r >> 1) * 8;
                    int b = nt * 8 + tig * 2 + (r & 1);
                    float v = my_tanh(acc[m][nt][r] + ebias[m * 2 + (r >> 1)]);
                    put_duo(SB + (u32)b * UP, hb + (u32)j, v, Pb);
                }
        // stage next inputs
        if (!last) {
            int b = tid >> 4, k8 = (tid & 15) * 8;
            const float* s = ((k8 < 64) ? pre_x : pre_y) +
                             (size_t)(t + 1) * 4096 * 64 + (size_t)(bbase + b) * 64 + (k8 & 63);
            stage8(SB + (u32)b * UP, (u32)k8, s, 768u);
        } else {
            int b = tid >> 4, k4 = (tid & 15) * 4;
            const float* s = fwd_x + (size_t)(bbase + b) * 64 + k4;
            stage4(SB + (u32)b * UP, (u32)k4, s, 640u);
        }
        __syncthreads();                       // new U visible
    }

    // ================= SSM + output projection =================
    for (int t = 0; t < 80; t++) {
        float acc[2][2][4] = {};
        gemm_g<20>(g_ssm, SB, warp, lane, acc);
        __syncthreads();
        // write h_t (ssm layout: h at slots 64.., part stride 640B)
#pragma unroll
        for (int m = 0; m < 2; m++)
#pragma unroll
            for (int nt = 0; nt < 2; nt++)
#pragma unroll
                for (int r = 0; r < 4; r++) {
                    int j = warp * 32 + m * 16 + gg + (r >> 1) * 8;
                    int b = nt * 8 + tig * 2 + (r & 1);
                    float v = acc[m][nt][r] + sbias[m * 2 + (r >> 1)];
                    put_duo(SB + (u32)b * UP, 64u + (u32)j, v, 640u);
                }
        __syncthreads();                       // h_t visible for C projection

        // C projection: 8 warps, jw = warp&3 (j-tile of 16), nh = warp>>2 (n-tile of 8)
        {
            const int jw = warp & 3, nh = warp >> 2;
            float accc[4] = {};
            const u32 bB = SB + (u32)(lane >> 2) * UP + (u32)(lane & 3) * 4u;
            const uint4* __restrict__ ap =
                (const uint4*)(g_cw + (u32)(jw * 512) + (u32)(lane * 16));
            uint4 Acur = __ldg(ap);            // chunk0 slab0
#pragma unroll 1
            for (int c = 0; c < 2; c++) {
#pragma unroll
                for (int sl = 0; sl < 16; sl++) {
                    uint4 Anext;
                    if (sl < 15)      Anext = __ldg(ap + (u32)c * 2048u + (u32)(sl + 1) * 128u);
                    else if (c == 0)  Anext = __ldg(ap + 2048u);
                    const u32* a0 = (const u32*)&Acur;
                    u32 su = (u32)c * 20u + 4u + (u32)sl;    // U h-region slabs
                    u32 bk = bB + su * 32u;
                    u32 b0, b1;
                    LDS32U(b0, bk + (u32)nh * (8u * UP));
                    LDS32U(b1, bk + (u32)nh * (8u * UP) + 16u);
                    MMA16816(accc, a0, b0, b1);
                    Acur = Anext;
                }
            }
            // epilogue: y -> gmem
            float* op = out + (size_t)t * 4096 * 64 + (size_t)bbase * 64;
#pragma unroll
            for (int r = 0; r < 4; r++) {
                int o = jw * 16 + gg + (r >> 1) * 8;
                int b = nh * 8 + tig * 2 + (r & 1);
                op[(size_t)b * 64 + o] = accc[r] + cb[r >> 1];
            }
        }
        // stage x_{t+1} (disjoint from h region; all threads)
        if (t < 79) {
            int b = tid >> 4, k4 = (tid & 15) * 4;
            const float* s = fwd_x + (size_t)(t + 1) * 4096 * 64 + (size_t)(bbase + b) * 64 + k4;
            stage4(SB + (u32)b * UP, (u32)k4, s, 640u);
        }
        __syncthreads();                       // x staged + C-proj reads done
    }
}

extern "C" void kernel_launch(void* const* d_in, const int* in_sizes, int n_in,
                              void* d_out, int out_size) {
    const float* pre_x = (const float*)d_in[0];
    const float* pre_y = (const float*)d_in[1];
    const float* fwd_x = (const float*)d_in[2];
    const float* A_w   = (const float*)d_in[3];
    const float* A_b   = (const float*)d_in[4];
    const float* B_w   = (const float*)d_in[5];
    const float* B_b   = (const float*)d_in[6];
    const float* C_w   = (const float*)d_in[7];
    const float* C_b   = (const float*)d_in[8];
    const float* W_ih  = (const float*)d_in[9];
    const float* b_ih  = (const float*)d_in[10];
    const float* W_hh  = (const float*)d_in[11];
    const float* b_hh  = (const float*)d_in[12];
    float* out = (float*)d_out;

    prep<<<1536, 256>>>(A_w, B_w, C_w, W_ih, W_hh);
    cudaFuncSetAttribute(ss_main, cudaFuncAttributeMaxDynamicSharedMemorySize, SMEM_TOTAL);
    ss_main<<<256, 256, SMEM_TOTAL>>>(pre_x, pre_y, fwd_x, A_b, B_b, C_b,
                                      b_ih, b_hh, out);
}

// round 16
// speedup vs baseline: 1.0258x; 1.0258x over previous
#include <cuda_runtime.h>
#include <cuda_fp16.h>
#include <math.h>

typedef unsigned long long u64;
typedef unsigned int u32;
typedef unsigned short u16;

// -------- prepped fragment-order weight streams (fp16 hi/lo, 2-term split) --------
__device__ __align__(128) unsigned char g_enc[393216];  // 12 chunks x 32KB, Ktilde=768
__device__ __align__(128) unsigned char g_ssm[327680];  // 10 chunks x 32KB, Ktilde=640
__device__ __align__(128) unsigned char g_cw[65536];    //  2 chunks x 32KB, Ktilde=512

__device__ __forceinline__ u16 hf_hi(float w) { return __half_as_ushort(__float2half_rn(w)); }
__device__ __forceinline__ u16 hf_lo(float w) {
    float h = __half2float(__float2half_rn(w));
    return __half_as_ushort(__float2half_rn(w - h));
}

// One thread per output fp16. Layout: chunk(32KB) -> slab(8KB enc/ssm, 2KB C) ->
// block(512B, (warp,mtile)) -> lane(16B) -> 4 regs x f16x2, matching the PTX
// m16n8k16 A-fragment: reg r holds (row + (r&1)*8, k + (r>>1)*8 + h).
__global__ void prep(const float* __restrict__ A_w, const float* __restrict__ B_w,
                     const float* __restrict__ C_w, const float* __restrict__ W_ih,
                     const float* __restrict__ W_hh) {
    u32 e = blockIdx.x * 256u + threadIdx.x;
    u32 kind, pos;
    if (e < 196608u)      { kind = 0; pos = e * 2u; }
    else if (e < 360448u) { kind = 1; pos = (e - 196608u) * 2u; }
    else if (e < 393216u) { kind = 2; pos = (e - 360448u) * 2u; }
    else return;
    u32 chunk = pos >> 15, inch = pos & 32767u;
    u32 slab, w, m, r3;
    if (kind < 2) { slab = inch >> 13; u32 r2 = inch & 8191u; u32 blk = r2 >> 9; w = blk >> 1; m = blk & 1u; r3 = r2 & 511u; }
    else          { slab = inch >> 11; u32 r2 = inch & 2047u; w = r2 >> 9; m = 0; r3 = r2 & 511u; }
    u32 t = r3 >> 4, r4 = r3 & 15u, reg = r4 >> 2, h = (r4 & 3u) >> 1;
    u32 row = (t >> 2) + (reg & 1u) * 8u;
    u32 kl  = (t & 3u) * 2u + (reg >> 1) * 8u + h;
    float src; u32 p;
    if (kind == 0) {
        u32 j = w * 32u + m * 16u + row;
        u32 kt = (chunk * 4u + slab) * 16u + kl;
        p = kt / 384u; u32 kk = kt % 384u;
        src = (kk < 128u) ? W_ih[j * 128u + kk] : W_hh[j * 256u + kk - 128u];
        *(u16*)(g_enc + pos) = p ? hf_lo(src) : hf_hi(src);
    } else if (kind == 1) {
        u32 j = w * 32u + m * 16u + row;
        u32 kt = (chunk * 4u + slab) * 16u + kl;
        p = kt / 320u; u32 kk = kt % 320u;
        src = (kk < 64u) ? B_w[j * 64u + kk] : A_w[j * 256u + kk - 64u];
        *(u16*)(g_ssm + pos) = p ? hf_lo(src) : hf_hi(src);
    } else {
        u32 o = w * 16u + row;
        u32 g4 = chunk * 16u + slab;
        p = g4 >> 4;
        u32 k = (g4 & 15u) * 16u + kl;        // 0..255
        src = C_w[o * 256u + k];
        *(u16*)(g_cw + pos) = p ? hf_lo(src) : hf_hi(src);
    }
}

// ---------------- PTX helpers ----------------
__device__ __forceinline__ u32 smem_u32(const void* p) {
    u32 a;
    asm("{ .reg .u64 t; cvta.to.shared.u64 t, %1; cvt.u32.u64 %0, t; }" : "=r"(a) : "l"(p));
    return a;
}
#define STS16(addr, v)  asm volatile("st.shared.u16 [%0], %1;" :: "r"(addr), "h"(v))
#define STS32(addr, f)  asm volatile("st.shared.f32 [%0], %1;" :: "r"(addr), "f"(f))
#define STSU32(addr, v) asm volatile("st.shared.u32 [%0], %1;" :: "r"(addr), "r"(v))
#define LDS32U(r, addr) asm volatile("ld.shared.u32 %0, [%1];" : "=r"(r) : "r"(addr))

#define MMA16816(c, a, b0, b1) \
    asm volatile("mma.sync.aligned.m16n8k16.row.col.f32.f16.f16.f32 " \
                 "{%0,%1,%2,%3},{%4,%5,%6,%7},{%8,%9},{%0,%1,%2,%3};" \
                 : "+f"((c)[0]), "+f"((c)[1]), "+f"((c)[2]), "+f"((c)[3]) \
                 : "r"((a)[0]), "r"((a)[1]), "r"((a)[2]), "r"((a)[3]), "r"(b0), "r"(b1))

__device__ __forceinline__ float my_tanh(float x) {
    float ax = fabsf(x);
    float e  = __expf(2.0f * ax);
    float r  = 1.0f - 2.0f / (e + 1.0f);
    return copysignf(r, x);
}

// ---------------- smem layout: U only ----------------
constexpr u32 UP = 1552;                 // U row pitch bytes (UP%128==16 -> conflict-free)
constexpr u32 OFF_U = 0;
constexpr u32 SMEM_TOTAL = 32 * UP;      // 49664

// dual-slot U write: hi at k, lo at k+P (Pb = part stride bytes)
__device__ __forceinline__ void put_duo(u32 ub, u32 k, float v, u32 Pb) {
    __half hb = __float2half_rn(v);
    u16 hi = __half_as_ushort(hb);
    u16 lo = __half_as_ushort(__float2half_rn(v - __half2float(hb)));
    u32 a = ub + k * 2u;
    STS16(a, hi); STS16(a + Pb, lo);
}

// stage 16/8 consecutive k-slots for one batch row: vector LDG + paired STS32
__device__ __forceinline__ void stage16(u32 ub, u32 k0, const float* s, u32 Pb) {
    float v[16];
    const float4* s4 = (const float4*)s;
#pragma unroll
    for (int q = 0; q < 4; q++) {
        float4 f = __ldg(s4 + q);
        v[q * 4] = f.x; v[q * 4 + 1] = f.y; v[q * 4 + 2] = f.z; v[q * 4 + 3] = f.w;
    }
#pragma unroll
    for (int i = 0; i < 16; i += 2) {
        __half a = __float2half_rn(v[i]), b = __float2half_rn(v[i + 1]);
        __half al = __float2half_rn(v[i] - __half2float(a));
        __half bl = __float2half_rn(v[i + 1] - __half2float(b));
        u32 hi = (u32)__half_as_ushort(a) | ((u32)__half_as_ushort(b) << 16);
        u32 lo = (u32)__half_as_ushort(al) | ((u32)__half_as_ushort(bl) << 16);
        u32 ad = ub + (k0 + (u32)i) * 2u;
        STSU32(ad, hi); STSU32(ad + Pb, lo);
    }
}
__device__ __forceinline__ void stage8(u32 ub, u32 k0, const float* s, u32 Pb) {
    float v[8];
    const float4* s4 = (const float4*)s;
#pragma unroll
    for (int q = 0; q < 2; q++) {
        float4 f = __ldg(s4 + q);
        v[q * 4] = f.x; v[q * 4 + 1] = f.y; v[q * 4 + 2] = f.z; v[q * 4 + 3] = f.w;
    }
#pragma unroll
    for (int i = 0; i < 8; i += 2) {
        __half a = __float2half_rn(v[i]), b = __float2half_rn(v[i + 1]);
        __half al = __float2half_rn(v[i] - __half2float(a));
        __half bl = __float2half_rn(v[i + 1] - __half2float(b));
        u32 hi = (u32)__half_as_ushort(a) | ((u32)__half_as_ushort(b) << 16);
        u32 lo = (u32)__half_as_ushort(al) | ((u32)__half_as_ushort(bl) << 16);
        u32 ad = ub + (k0 + (u32)i) * 2u;
        STSU32(ad, hi); STSU32(ad + Pb, lo);
    }
}

// ---- half-chunk (2-slab) pipeline helpers: statically-named buffers only ----
// Each half = 2 slabs; per warp: 4 LDG.128 (2 mtile-frags x 2 slabs).
__device__ __forceinline__ void half_load(uint4 (&H)[4], const uint4* __restrict__ ap,
                                          u32 half) {
    const uint4* p = ap + half * 1024u;          // 2 slabs * 8192B = 1024 uint4
    H[0] = __ldg(p);
    H[1] = __ldg(p + 32);
    H[2] = __ldg(p + 512);
    H[3] = __ldg(p + 512 + 32);
}
__device__ __forceinline__ void half_compute(const uint4 (&H)[4], u32 bB, u32 kt0,
                                             float acc[2][4][4]) {
#pragma unroll
    for (int sl = 0; sl < 2; sl++) {
        u32 bk = bB + (kt0 + (u32)sl * 16u) * 2u;
        u32 b0[4], b1[4];
#pragma unroll
        for (int nt = 0; nt < 4; nt++) {
            LDS32U(b0[nt], bk + (u32)nt * (8u * UP));
            LDS32U(b1[nt], bk + (u32)nt * (8u * UP) + 16u);
        }
        const u32* a0 = (const u32*)&H[sl * 2];
        const u32* a1 = (const u32*)&H[sl * 2 + 1];
#pragma unroll
        for (int nt = 0; nt < 4; nt++) {
            MMA16816(acc[0][nt], a0, b0[nt], b1[nt]);
            MMA16816(acc[1][nt], a1, b0[nt], b1[nt]);
        }
    }
}

// main GEMM: 4-buffer half-chunk rotation, prefetch distance 3 halves
// (~450-600 cyc of slack). NHALF must be divisible by 4.
template <int NHALF>
__device__ __forceinline__ void gemm_g(const unsigned char* __restrict__ gw,
                                       u32 Ub, int warp, int lane,
                                       float acc[2][4][4]) {
    static_assert(NHALF % 4 == 0, "NHALF divisible by 4");
    const u32 bB = Ub + (u32)(lane >> 2) * UP + (u32)(lane & 3) * 4u;
    const uint4* __restrict__ ap =
        (const uint4*)(gw + (u32)(warp * 1024) + (u32)(lane * 16));
    uint4 H0[4], H1[4], H2[4], H3[4];
    half_load(H0, ap, 0);
    half_load(H1, ap, 1);
    half_load(H2, ap, 2);
#pragma unroll 1
    for (int h = 0; h < NHALF; h += 4) {
        if (h + 3 < NHALF) half_load(H3, ap, (u32)(h + 3));
        half_compute(H0, bB, (u32)h * 32u, acc);
        if (h + 4 < NHALF) half_load(H0, ap, (u32)(h + 4));
        half_compute(H1, bB, (u32)(h + 1) * 32u, acc);
        if (h + 5 < NHALF) half_load(H1, ap, (u32)(h + 5));
        half_compute(H2, bB, (u32)(h + 2) * 32u, acc);
        if (h + 6 < NHALF) half_load(H2, ap, (u32)(h + 6));
        half_compute(H3, bB, (u32)(h + 3) * 32u, acc);
    }
}

__global__ __launch_bounds__(256, 1) void ss_main(
    const float* __restrict__ pre_x, const float* __restrict__ pre_y,
    const float* __restrict__ fwd_x,
    const float* __restrict__ A_b, const float* __restrict__ B_b,
    const float* __restrict__ C_b, const float* __restrict__ b_ih,
    const float* __restrict__ b_hh, float* __restrict__ out)
{
    extern __shared__ char smraw[];
    const u32 SB = smem_u32(smraw);
    const int tid = threadIdx.x, lane = tid & 31, warp = tid >> 5;
    const int bbase = blockIdx.x * 32;
    const int gg = lane >> 2, tig = lane & 3;

    // zero U
    for (int i = tid; i < (int)(SMEM_TOTAL / 4); i += 256) STS32(SB + (u32)i * 4u, 0.0f);
    // stage x0,y0 (enc layout: x at k 0..63, y at 64..127; part stride 768B)
    {
        int b = tid >> 3, k16 = (tid & 7) * 16;
        const float* s = ((k16 < 64) ? pre_x : pre_y) + (size_t)(bbase + b) * 64 + (k16 & 63);
        stage16(SB + (u32)b * UP, (u32)k16, s, 768u);
    }

    // biases in regs
    float ebias[4], sbias[4], cb[2];
#pragma unroll
    for (int m = 0; m < 2; m++)
#pragma unroll
        for (int rh = 0; rh < 2; rh++) {
            int j = warp * 32 + m * 16 + gg + rh * 8;
            ebias[m * 2 + rh] = b_ih[j] + b_hh[j];
            sbias[m * 2 + rh] = A_b[j] + B_b[j];
        }
    cb[0] = C_b[(warp & 3) * 16 + gg];
    cb[1] = C_b[(warp & 3) * 16 + gg + 8];
    __syncthreads();

    // ================= encoder =================
    for (int t = 0; t < 64; t++) {
        float acc[2][4][4] = {};
        gemm_g<24>(g_enc, SB, warp, lane, acc);
        __syncthreads();                       // all reads of old U done
        const bool last = (t == 63);
        const u32 hb = last ? 64u : 128u;      // h base slot (ssm vs enc layout)
        const u32 Pb = last ? 640u : 768u;     // part stride bytes
#pragma unroll
        for (int m = 0; m < 2; m++)
#pragma unroll
            for (int nt = 0; nt < 4; nt++)
#pragma unroll
                for (int r = 0; r < 4; r++) {
                    int j = warp * 32 + m * 16 + gg + (r >> 1) * 8;
                    int b = nt * 8 + tig * 2 + (r & 1);
                    float v = my_tanh(acc[m][nt][r] + ebias[m * 2 + (r >> 1)]);
                    put_duo(SB + (u32)b * UP, hb + (u32)j, v, Pb);
                }
        // stage next inputs
        if (!last) {
            int b = tid >> 3, k16 = (tid & 7) * 16;
            const float* s = ((k16 < 64) ? pre_x : pre_y) +
                             (size_t)(t + 1) * 4096 * 64 + (size_t)(bbase + b) * 64 + (k16 & 63);
            stage16(SB + (u32)b * UP, (u32)k16, s, 768u);
        } else {
            int b = tid >> 3, k16 = (tid & 7) * 16;
            if (k16 < 64) {
                const float* s = fwd_x + (size_t)(bbase + b) * 64 + k16;
                stage16(SB + (u32)b * UP, (u32)k16, s, 640u);
            }
        }
        __syncthreads();                       // new U visible
    }

    // ================= SSM + output projection =================
    for (int t = 0; t < 80; t++) {
        float acc[2][4][4] = {};
        gemm_g<20>(g_ssm, SB, warp, lane, acc);
        __syncthreads();
        // write h_t (ssm layout: h at slots 64.., part stride 640B)
#pragma unroll
        for (int m = 0; m < 2; m++)
#pragma unroll
            for (int nt = 0; nt < 4; nt++)
#pragma unroll
                for (int r = 0; r < 4; r++) {
                    int j = warp * 32 + m * 16 + gg + (r >> 1) * 8;
                    int b = nt * 8 + tig * 2 + (r & 1);
                    float v = acc[m][nt][r] + sbias[m * 2 + (r >> 1)];
                    put_duo(SB + (u32)b * UP, 64u + (u32)j, v, 640u);
                }
        __syncthreads();                       // h_t visible for C projection

        // C projection split across all 8 warps: j-tile = warp&3, n-half = warp>>2
        {
            const int jw = warp & 3, nh = warp >> 2;
            float accc[2][4] = {};
            const u32 bB = SB + (u32)(lane >> 2) * UP + (u32)(lane & 3) * 4u;
            const uint4* __restrict__ ap =
                (const uint4*)(g_cw + (u32)(jw * 512) + (u32)(lane * 16));
            uint4 Acur = __ldg(ap);            // chunk0 slab0
#pragma unroll 1
            for (int c = 0; c < 2; c++) {
#pragma unroll
                for (int sl = 0; sl < 16; sl++) {
                    uint4 Anext;
                    if (sl < 15)      Anext = __ldg(ap + (u32)c * 2048u + (u32)(sl + 1) * 128u);
                    else if (c == 0)  Anext = __ldg(ap + 2048u);
                    const u32* a0 = (const u32*)&Acur;
                    u32 su = (u32)c * 20u + 4u + (u32)sl;    // U h-region slabs
                    u32 bk = bB + su * 32u;
#pragma unroll
                    for (int h = 0; h < 2; h++) {
                        int nt = nh * 2 + h;
                        u32 b0, b1;
                        LDS32U(b0, bk + (u32)nt * (8u * UP));
                        LDS32U(b1, bk + (u32)nt * (8u * UP) + 16u);
                        MMA16816(accc[h], a0, b0, b1);
                    }
                    Acur = Anext;
                }
            }
            // epilogue: y -> gmem
            float* op = out + (size_t)t * 4096 * 64 + (size_t)bbase * 64;
#pragma unroll
            for (int h = 0; h < 2; h++)
#pragma unroll
                for (int r = 0; r < 4; r++) {
                    int o = jw * 16 + gg + (r >> 1) * 8;
                    int b = (nh * 2 + h) * 8 + tig * 2 + (r & 1);
                    op[(size_t)b * 64 + o] = accc[h][r] + cb[r >> 1];
                }
        }
        // stage x_{t+1} (all threads)
        if (t < 79) {
            int b = tid >> 3, k8 = (tid & 7) * 8;
            const float* s = fwd_x + (size_t)(t + 1) * 4096 * 64 + (size_t)(bbase + b) * 64 + k8;
            stage8(SB + (u32)b * UP, (u32)k8, s, 640u);
        }
        __syncthreads();                       // x staged + C-proj reads done
    }
}

extern "C" void kernel_launch(void* const* d_in, const int* in_sizes, int n_in,
                              void* d_out, int out_size) {
    const float* pre_x = (const float*)d_in[0];
    const float* pre_y = (const float*)d_in[1];
    const float* fwd_x = (const float*)d_in[2];
    const float* A_w   = (const float*)d_in[3];
    const float* A_b   = (const float*)d_in[4];
    const float* B_w   = (const float*)d_in[5];
    const float* B_b   = (const float*)d_in[6];
    const float* C_w   = (const float*)d_in[7];
    const float* C_b   = (const float*)d_in[8];
    const float* W_ih  = (const float*)d_in[9];
    const float* b_ih  = (const float*)d_in[10];
    const float* W_hh  = (const float*)d_in[11];
    const float* b_hh  = (const float*)d_in[12];
    float* out = (float*)d_out;

    prep<<<1536, 256>>>(A_w, B_w, C_w, W_ih, W_hh);
    cudaFuncSetAttribute(ss_main, cudaFuncAttributeMaxDynamicSharedMemorySize, SMEM_TOTAL);
    ss_main<<<128, 256, SMEM_TOTAL>>>(pre_x, pre_y, fwd_x, A_b, B_b, C_b,
                                      b_ih, b_hh, out);
}

// round 17
// speedup vs baseline: 1.1354x; 1.1068x over previous
#include <cuda_runtime.h>
#include <cuda_fp16.h>
#include <math.h>

typedef unsigned long long u64;
typedef unsigned int u32;
typedef unsigned short u16;

// -------- prepped streams --------
__device__ __align__(128) unsigned char g_enc[393216];   // encoder: 12 chunks x 32KB, Ktilde=768
__device__ __align__(128) unsigned char g_blk[1048576];  // blocked ssm: 64 slabs x 16KB (M=512,Ktilde=1024)

// -------- prep scratch (fp32) --------
__device__ float sA2[256 * 256];
__device__ float sAB[256 * 64];
__device__ float sCA[64 * 256];
__device__ float sCA2[64 * 256];
__device__ float G32[512 * 512];
__device__ float d_bias2[512];

__device__ __forceinline__ u16 hf_hi(float w) { return __half_as_ushort(__float2half_rn(w)); }
__device__ __forceinline__ u16 hf_lo(float w) {
    float h = __half2float(__float2half_rn(w));
    return __half_as_ushort(__float2half_rn(w - h));
}

// ---------------- prep: encoder pack (unchanged layout from R11) ----------------
__global__ void pack_enc(const float* __restrict__ W_ih, const float* __restrict__ W_hh) {
    u32 e = blockIdx.x * 256u + threadIdx.x;
    if (e >= 196608u) return;
    u32 pos = e * 2u;
    u32 chunk = pos >> 15, inch = pos & 32767u;
    u32 slab = inch >> 13; u32 r2 = inch & 8191u; u32 blk = r2 >> 9;
    u32 w = blk >> 1, m = blk & 1u, r3 = r2 & 511u;
    u32 t = r3 >> 4, r4 = r3 & 15u, reg = r4 >> 2, h = (r4 & 3u) >> 1;
    u32 row = (t >> 2) + (reg & 1u) * 8u;
    u32 kl  = (t & 3u) * 2u + (reg >> 1) * 8u + h;
    u32 j = w * 32u + m * 16u + row;
    u32 kt = (chunk * 4u + slab) * 16u + kl;
    u32 p = kt / 384u; u32 kk = kt % 384u;
    float src = (kk < 128u) ? W_ih[j * 128u + kk] : W_hh[j * 256u + kk - 128u];
    *(u16*)(g_enc + pos) = p ? hf_lo(src) : hf_hi(src);
}

// ---------------- prep: matrix-product levels (all K=256 dots) ----------------
__device__ __forceinline__ float dot256(const float* __restrict__ X, int i,
                                        const float* __restrict__ Y, int j, int ldy) {
    float s = 0.0f;
#pragma unroll 8
    for (int k = 0; k < 256; k++) s += X[i * 256 + k] * Y[k * ldy + j];
    return s;
}

__global__ void matlevel(int level, const float* __restrict__ Aw,
                         const float* __restrict__ Bw, const float* __restrict__ Cw) {
    int blk = blockIdx.x, tid = threadIdx.x;
    if (level == 1) {
        if (blk < 256) {                    // A2 = A*A -> sA2
            int idx = blk * 256 + tid, i = idx >> 8, j = idx & 255;
            sA2[idx] = dot256(Aw, i, Aw, j, 256);
        } else if (blk < 320) {             // AB = A*B -> sAB
            int idx = (blk - 256) * 256 + tid, i = idx >> 6, j = idx & 63;
            sAB[idx] = dot256(Aw, i, Bw, j, 64);
        } else if (blk < 384) {             // CA = C*A -> sCA
            int idx = (blk - 320) * 256 + tid, i = idx >> 8, j = idx & 255;
            sCA[idx] = dot256(Cw, i, Aw, j, 256);
        } else if (blk < 448) {             // CB -> 4 diagonal tiles of G32
            int q = (blk - 384) >> 4;
            int idx = ((blk - 384) & 15) * 256 + tid, i = idx >> 6, j = idx & 63;
            G32[(256 + 64 * q + i) * 512 + 256 + 64 * q + j] = dot256(Cw, i, Bw, j, 64);
        } else if (blk < 512) {             // copy B -> G32[0][448]
            int idx = (blk - 448) * 256 + tid, i = idx >> 6, j = idx & 63;
            G32[i * 512 + 448 + j] = Bw[i * 64 + j];
        } else {                            // zero tiles (y-part strictly-upper)
            int z = (blk - 512) * 256 + tid, r, c;
            if (z < 12288)      { r = 256 + z / 192;          c = 320 + z % 192; }
            else if (z < 20480) { int q = z - 12288; r = 320 + q / 128; c = 384 + q % 128; }
            else                { int q = z - 20480; r = 384 + q / 64;  c = 448 + q % 64; }
            G32[r * 512 + c] = 0.0f;
        }
    } else if (level == 2) {
        if (blk < 256) {                    // A4 = A2*A2 -> G32[0][0]
            int idx = blk * 256 + tid, i = idx >> 8, j = idx & 255;
            G32[i * 512 + j] = dot256(sA2, i, sA2, j, 256);
        } else if (blk < 320) {             // A3B = A2*AB -> G32[0][256]
            int idx = (blk - 256) * 256 + tid, i = idx >> 6, j = idx & 63;
            G32[i * 512 + 256 + j] = dot256(sA2, i, sAB, j, 64);
        } else if (blk < 384) {             // A2B = A2*B -> G32[0][320]
            int idx = (blk - 320) * 256 + tid, i = idx >> 6, j = idx & 63;
            G32[i * 512 + 320 + j] = dot256(sA2, i, Bw, j, 64);
        } else if (blk < 448) {             // copy AB -> G32[0][384]
            int idx = (blk - 384) * 256 + tid, i = idx >> 6, j = idx & 63;
            G32[i * 512 + 384 + j] = sAB[i * 64 + j];
        } else if (blk < 512) {             // CA2 = CA*A -> sCA2 and G32[320][0]
            int idx = (blk - 448) * 256 + tid, i = idx >> 8, j = idx & 255;
            float v = dot256(sCA, i, Aw, j, 256);
            sCA2[idx] = v;
            G32[(320 + i) * 512 + j] = v;
        } else if (blk < 576) {             // CA3 = CA*A2 -> G32[384][0]
            int idx = (blk - 512) * 256 + tid, i = idx >> 8, j = idx & 255;
            G32[(384 + i) * 512 + j] = dot256(sCA, i, sA2, j, 256);
        } else if (blk < 624) {             // CAB = CA*B -> (320,256),(384,320),(448,384)
            int q = (blk - 576) >> 4;
            int idx = ((blk - 576) & 15) * 256 + tid, i = idx >> 6, j = idx & 63;
            float v = dot256(sCA, i, Bw, j, 64);
            int r0 = 320 + 64 * q, c0 = 256 + 64 * q;
            G32[(r0 + i) * 512 + c0 + j] = v;
        } else if (blk < 656) {             // CA2B = CA*AB -> (384,256),(448,320)
            int q = (blk - 624) >> 4;
            int idx = ((blk - 624) & 15) * 256 + tid, i = idx >> 6, j = idx & 63;
            float v = dot256(sCA, i, sAB, j, 64);
            int r0 = 384 + 64 * q, c0 = 256 + 64 * q;
            G32[(r0 + i) * 512 + c0 + j] = v;
        } else {                            // copy CA -> G32[256][0]
            int idx = (blk - 656) * 256 + tid, i = idx >> 8, j = idx & 255;
            G32[(256 + i) * 512 + j] = sCA[i * 256 + j];
        }
    } else {
        if (blk < 64) {                     // CA4 = CA2*A2 -> G32[448][0]
            int idx = blk * 256 + tid, i = idx >> 8, j = idx & 255;
            G32[(448 + i) * 512 + j] = dot256(sCA2, i, sA2, j, 256);
        } else {                            // CA3B = CA2*AB -> G32[448][256]
            int idx = (blk - 64) * 256 + tid, i = idx >> 6, j = idx & 63;
            G32[(448 + i) * 512 + 256 + j] = dot256(sCA2, i, sAB, j, 64);
        }
    }
}

// bias chain: w_k = sum_{j<k} A^j beta;  gamma = w_4;  psi_k = C w_k + C_b
__global__ void biasprep(const float* __restrict__ Aw, const float* __restrict__ A_b,
                         const float* __restrict__ B_b, const float* __restrict__ Cw,
                         const float* __restrict__ C_b) {
    __shared__ float w[256];
    int tid = threadIdx.x;
    float beta = A_b[tid] + B_b[tid];
    w[tid] = beta;
    __syncthreads();
    for (int k = 1; k <= 4; k++) {
        if (tid < 64) {
            float s = C_b[tid];
            for (int j = 0; j < 256; j++) s += Cw[tid * 256 + j] * w[j];
            d_bias2[256 + 64 * (k - 1) + tid] = s;
        }
        if (k < 4) {
            float s = beta;
            for (int j = 0; j < 256; j++) s += Aw[tid * 256 + j] * w[j];
            __syncthreads();
            w[tid] = s;
            __syncthreads();
        }
    }
    d_bias2[tid] = w[tid];   // gamma
}

// pack G32 (fp32 512x512) into fragment-order fp16 hi/lo stream g_blk
__global__ void pack_blk() {
    u32 pos = (blockIdx.x * 256u + threadIdx.x) * 2u;
    u32 slab = pos >> 14, r2 = pos & 16383u;
    u32 blk = r2 >> 9, r3 = r2 & 511u;
    u32 t = r3 >> 4, r4 = r3 & 15u, reg = r4 >> 2, h = (r4 & 3u) >> 1;
    u32 row = (t >> 2) + (reg & 1u) * 8u;
    u32 kl  = (t & 3u) * 2u + (reg >> 1) * 8u + h;
    u32 m = blk * 16u + row;
    u32 ktilde = slab * 16u + kl;
    u32 p = ktilde >> 9; u32 k = ktilde & 511u;
    float v = G32[m * 512u + k];
    *(u16*)(g_blk + pos) = p ? hf_lo(v) : hf_hi(v);
}

// ---------------- PTX helpers ----------------
__device__ __forceinline__ u32 smem_u32(const void* p) {
    u32 a;
    asm("{ .reg .u64 t; cvta.to.shared.u64 t, %1; cvt.u32.u64 %0, t; }" : "=r"(a) : "l"(p));
    return a;
}
#define STS16(addr, v)  asm volatile("st.shared.u16 [%0], %1;" :: "r"(addr), "h"(v))
#define STS32(addr, f)  asm volatile("st.shared.f32 [%0], %1;" :: "r"(addr), "f"(f))
#define STSU32(addr, v) asm volatile("st.shared.u32 [%0], %1;" :: "r"(addr), "r"(v))
#define LDS32U(r, addr) asm volatile("ld.shared.u32 %0, [%1];" : "=r"(r) : "r"(addr))

#define MMA16816(c, a, b0, b1) \
    asm volatile("mma.sync.aligned.m16n8k16.row.col.f32.f16.f16.f32 " \
                 "{%0,%1,%2,%3},{%4,%5,%6,%7},{%8,%9},{%0,%1,%2,%3};" \
                 : "+f"((c)[0]), "+f"((c)[1]), "+f"((c)[2]), "+f"((c)[3]) \
                 : "r"((a)[0]), "r"((a)[1]), "r"((a)[2]), "r"((a)[3]), "r"(b0), "r"(b1))

__device__ __forceinline__ float my_tanh(float x) {
    float ax = fabsf(x);
    float e  = __expf(2.0f * ax);
    float r  = 1.0f - 2.0f / (e + 1.0f);
    return copysignf(r, x);
}

// ---------------- smem: U, 32 rows x 1032 fp16 slots ----------------
constexpr u32 UP = 2064;                 // UP%128==16 -> conflict-free
constexpr u32 SMEM_TOTAL = 32 * UP;      // 66048

__device__ __forceinline__ void put_duo(u32 ub, u32 k, float v, u32 Pb) {
    __half hb = __float2half_rn(v);
    u16 hi = __half_as_ushort(hb);
    u16 lo = __half_as_ushort(__float2half_rn(v - __half2float(hb)));
    u32 a = ub + k * 2u;
    STS16(a, hi); STS16(a + Pb, lo);
}

__device__ __forceinline__ void stage16(u32 ub, u32 k0, const float* s, u32 Pb) {
    float v[16];
    const float4* s4 = (const float4*)s;
#pragma unroll
    for (int q = 0; q < 4; q++) {
        float4 f = __ldg(s4 + q);
        v[q * 4] = f.x; v[q * 4 + 1] = f.y; v[q * 4 + 2] = f.z; v[q * 4 + 3] = f.w;
    }
#pragma unroll
    for (int i = 0; i < 16; i += 2) {
        __half a = __float2half_rn(v[i]), b = __float2half_rn(v[i + 1]);
        __half al = __float2half_rn(v[i] - __half2float(a));
        __half bl = __float2half_rn(v[i + 1] - __half2float(b));
        u32 hi = (u32)__half_as_ushort(a) | ((u32)__half_as_ushort(b) << 16);
        u32 lo = (u32)__half_as_ushort(al) | ((u32)__half_as_ushort(bl) << 16);
        u32 ad = ub + (k0 + (u32)i) * 2u;
        STSU32(ad, hi); STSU32(ad + Pb, lo);
    }
}
__device__ __forceinline__ void stage8(u32 ub, u32 k0, const float* s, u32 Pb) {
    float v[8];
    const float4* s4 = (const float4*)s;
#pragma unroll
    for (int q = 0; q < 2; q++) {
        float4 f = __ldg(s4 + q);
        v[q * 4] = f.x; v[q * 4 + 1] = f.y; v[q * 4 + 2] = f.z; v[q * 4 + 3] = f.w;
    }
#pragma unroll
    for (int i = 0; i < 8; i += 2) {
        __half a = __float2half_rn(v[i]), b = __float2half_rn(v[i + 1]);
        __half al = __float2half_rn(v[i] - __half2float(a));
        __half bl = __float2half_rn(v[i + 1] - __half2float(b));
        u32 hi = (u32)__half_as_ushort(a) | ((u32)__half_as_ushort(b) << 16);
        u32 lo = (u32)__half_as_ushort(al) | ((u32)__half_as_ushort(bl) << 16);
        u32 ad = ub + (k0 + (u32)i) * 2u;
        STSU32(ad, hi); STSU32(ad + Pb, lo);
    }
}

// ---- encoder GEMM (R11 verbatim, UP-agnostic) ----
__device__ __forceinline__ void chunk_load(uint4 (&A)[8], const uint4* __restrict__ ap) {
#pragma unroll
    for (int sl = 0; sl < 4; sl++) {
        A[sl * 2]     = __ldg(ap + sl * 512);
        A[sl * 2 + 1] = __ldg(ap + sl * 512 + 32);
    }
}
__device__ __forceinline__ void chunk_compute(const uint4 (&A)[8], u32 bB, u32& kt,
                                              float acc[2][4][4]) {
#pragma unroll
    for (int sl = 0; sl < 4; sl++) {
        u32 bk = bB + kt * 2u;
        u32 b0[4], b1[4];
#pragma unroll
        for (int nt = 0; nt < 4; nt++) {
            LDS32U(b0[nt], bk + (u32)nt * (8u * UP));
            LDS32U(b1[nt], bk + (u32)nt * (8u * UP) + 16u);
        }
        const u32* a0 = (const u32*)&A[sl * 2];
        const u32* a1 = (const u32*)&A[sl * 2 + 1];
#pragma unroll
        for (int nt = 0; nt < 4; nt++) {
            MMA16816(acc[0][nt], a0, b0[nt], b1[nt]);
            MMA16816(acc[1][nt], a1, b0[nt], b1[nt]);
        }
        kt += 16;
    }
}
template <int NCH>
__device__ __forceinline__ void gemm_enc(u32 Ub, int warp, int lane, float acc[2][4][4]) {
    const u32 bB = Ub + (u32)(lane >> 2) * UP + (u32)(lane & 3) * 4u;
    const uint4* __restrict__ ap =
        (const uint4*)(g_enc + (u32)(warp * 1024) + (u32)(lane * 16));
    uint4 A0[8], A1[8];
    chunk_load(A0, ap);
    u32 kt = 0;
#pragma unroll 1
    for (int c = 0; c < NCH; c += 2) {
        chunk_load(A1, ap + (u32)(c + 1) * 2048u);
        chunk_compute(A0, bB, kt, acc);
        if (c + 2 < NCH) chunk_load(A0, ap + (u32)(c + 2) * 2048u);
        chunk_compute(A1, bB, kt, acc);
    }
}

// ---- blocked-SSM GEMM: M=512, 64 slabs x 16KB; warp owns m-tiles 4w..4w+3 ----
__device__ __forceinline__ void load2b(uint4 (&A)[8], const uint4* __restrict__ ap, u32 s) {
    const uint4* p = ap + s * 1024u;
#pragma unroll
    for (int sl = 0; sl < 2; sl++)
#pragma unroll
        for (int mt = 0; mt < 4; mt++)
            A[sl * 4 + mt] = __ldg(p + (u32)sl * 1024u + (u32)mt * 32u);
}
__device__ __forceinline__ void comp2b(const uint4 (&A)[8], u32 bB, u32 s,
                                       float acc[4][4][4]) {
#pragma unroll
    for (int sl = 0; sl < 2; sl++) {
        u32 bk = bB + (s + (u32)sl) * 32u;
        u32 b0[4], b1[4];
#pragma unroll
        for (int nt = 0; nt < 4; nt++) {
            LDS32U(b0[nt], bk + (u32)nt * (8u * UP));
            LDS32U(b1[nt], bk + (u32)nt * (8u * UP) + 16u);
        }
#pragma unroll
        for (int mt = 0; mt < 4; mt++) {
            const u32* a0 = (const u32*)&A[sl * 4 + mt];
#pragma unroll
            for (int nt = 0; nt < 4; nt++)
                MMA16816(acc[mt][nt], a0, b0[nt], b1[nt]);
        }
    }
}
__device__ __forceinline__ void gemm_blk(u32 Ub, int warp, int lane, float acc[4][4][4]) {
    const u32 bB = Ub + (u32)(lane >> 2) * UP + (u32)(lane & 3) * 4u;
    const uint4* __restrict__ ap =
        (const uint4*)(g_blk + (u32)(warp * 2048) + (u32)(lane * 16));
    uint4 A0[8], A1[8];
    load2b(A0, ap, 0);
#pragma unroll 1
    for (u32 s = 0; s < 64; s += 4) {
        load2b(A1, ap, s + 2);
        comp2b(A0, bB, s, acc);
        if (s + 4 < 64) load2b(A0, ap, s + 4);
        comp2b(A1, bB, s + 2, acc);
    }
}

__global__ __launch_bounds__(256, 1) void ss_main(
    const float* __restrict__ pre_x, const float* __restrict__ pre_y,
    const float* __restrict__ fwd_x,
    const float* __restrict__ b_ih, const float* __restrict__ b_hh,
    float* __restrict__ out)
{
    extern __shared__ char smraw[];
    const u32 SB = smem_u32(smraw);
    const int tid = threadIdx.x, lane = tid & 31, warp = tid >> 5;
    const int bbase = blockIdx.x * 32;
    const int gg = lane >> 2, tig = lane & 3;

    // zero U
    for (int i = tid; i < (int)(SMEM_TOTAL / 4); i += 256) STS32(SB + (u32)i * 4u, 0.0f);
    // stage x0,y0 (enc layout: x slots 0..63, y 64..127, part stride 768B)
    {
        int b = tid >> 3, k16 = (tid & 7) * 16;
        const float* s = ((k16 < 64) ? pre_x : pre_y) + (size_t)(bbase + b) * 64 + (k16 & 63);
        stage16(SB + (u32)b * UP, (u32)k16, s, 768u);
    }

    // encoder biases
    float ebias[4];
#pragma unroll
    for (int m = 0; m < 2; m++)
#pragma unroll
        for (int rh = 0; rh < 2; rh++) {
            int j = warp * 32 + m * 16 + gg + rh * 8;
            ebias[m * 2 + rh] = b_ih[j] + b_hh[j];
        }
    // blocked-ssm biases: warp owns rows 64w..64w+63
    float bb[4][2];
#pragma unroll
    for (int mt = 0; mt < 4; mt++)
#pragma unroll
        for (int rh = 0; rh < 2; rh++)
            bb[mt][rh] = d_bias2[warp * 64 + mt * 16 + gg + rh * 8];
    __syncthreads();

    // ================= encoder (R11 structure) =================
    for (int t = 0; t < 64; t++) {
        float acc[2][4][4] = {};
        gemm_enc<12>(SB, warp, lane, acc);
        __syncthreads();                       // all reads of old U done
        const bool last = (t == 63);
        const u32 hb = last ? 0u : 128u;       // h slot base (blk layout s at 0)
        const u32 Pb = last ? 1024u : 768u;
#pragma unroll
        for (int m = 0; m < 2; m++)
#pragma unroll
            for (int nt = 0; nt < 4; nt++)
#pragma unroll
                for (int r = 0; r < 4; r++) {
                    int j = warp * 32 + m * 16 + gg + (r >> 1) * 8;
                    int b = nt * 8 + tig * 2 + (r & 1);
                    float v = my_tanh(acc[m][nt][r] + ebias[m * 2 + (r >> 1)]);
                    put_duo(SB + (u32)b * UP, hb + (u32)j, v, Pb);
                }
        if (!last) {
            int b = tid >> 3, k16 = (tid & 7) * 16;
            const float* s = ((k16 < 64) ? pre_x : pre_y) +
                             (size_t)(t + 1) * 4096 * 64 + (size_t)(bbase + b) * 64 + (k16 & 63);
            stage16(SB + (u32)b * UP, (u32)k16, s, 768u);
        } else {
            // stage x_1..x_4 of block 0 into slots 256+64j (part stride 1024B)
            int b = tid >> 3, k8 = (tid & 7) * 8;
#pragma unroll
            for (int j = 0; j < 4; j++) {
                const float* s = fwd_x + (size_t)j * 4096 * 64 + (size_t)(bbase + b) * 64 + k8;
                stage8(SB + (u32)b * UP, 256u + 64u * (u32)j + (u32)k8, s, 1024u);
            }
        }
        __syncthreads();
    }

    // ======= blocked SSM: 20 blocks of 4 steps, one M=512 GEMM each =======
#pragma unroll 1
    for (int i = 0; i < 20; i++) {
        float acc[4][4][4] = {};
        gemm_blk(SB, warp, lane, acc);
        __syncthreads();                       // all U reads done
        if (warp < 4) {
            // s' rows [0,256): write back into U slots [0,256)
#pragma unroll
            for (int mt = 0; mt < 4; mt++)
#pragma unroll
                for (int nt = 0; nt < 4; nt++)
#pragma unroll
                    for (int r = 0; r < 4; r++) {
                        int row = warp * 64 + mt * 16 + gg + (r >> 1) * 8;
                        int b = nt * 8 + tig * 2 + (r & 1);
                        put_duo(SB + (u32)b * UP, (u32)row,
                                acc[mt][nt][r] + bb[mt][r >> 1], 1024u);
                    }
        } else {
            // y rows: warp w -> y_{4i + (w-4) + 1} -> out step t0 = 4i + (w-4)
            float* op = out + (size_t)(4 * i + warp - 4) * 4096 * 64 + (size_t)bbase * 64;
#pragma unroll
            for (int mt = 0; mt < 4; mt++)
#pragma unroll
                for (int nt = 0; nt < 4; nt++)
#pragma unroll
                    for (int r = 0; r < 4; r++) {
                        int o = mt * 16 + gg + (r >> 1) * 8;
                        int b = nt * 8 + tig * 2 + (r & 1);
                        op[(size_t)b * 64 + o] = acc[mt][nt][r] + bb[mt][r >> 1];
                    }
        }
        // stage x for next block into slots [256,512)
        if (i < 19) {
            int b = tid >> 3, k8 = (tid & 7) * 8;
#pragma unroll
            for (int j = 0; j < 4; j++) {
                const float* s = fwd_x + (size_t)(4 * i + 4 + j) * 4096 * 64 +
                                 (size_t)(bbase + b) * 64 + k8;
                stage8(SB + (u32)b * UP, 256u + 64u * (u32)j + (u32)k8, s, 1024u);
            }
        }
        __syncthreads();
    }
}

extern "C" void kernel_launch(void* const* d_in, const int* in_sizes, int n_in,
                              void* d_out, int out_size) {
    const float* pre_x = (const float*)d_in[0];
    const float* pre_y = (const float*)d_in[1];
    const float* fwd_x = (const float*)d_in[2];
    const float* A_w   = (const float*)d_in[3];
    const float* A_b   = (const float*)d_in[4];
    const float* B_w   = (const float*)d_in[5];
    const float* B_b   = (const float*)d_in[6];
    const float* C_w   = (const float*)d_in[7];
    const float* C_b   = (const float*)d_in[8];
    const float* W_ih  = (const float*)d_in[9];
    const float* b_ih  = (const float*)d_in[10];
    const float* W_hh  = (const float*)d_in[11];
    const float* b_hh  = (const float*)d_in[12];
    float* out = (float*)d_out;

    pack_enc<<<768, 256>>>(W_ih, W_hh);
    matlevel<<<608, 256>>>(1, A_w, B_w, C_w);
    matlevel<<<720, 256>>>(2, A_w, B_w, C_w);
    matlevel<<<80, 256>>>(3, A_w, B_w, C_w);
    biasprep<<<1, 256>>>(A_w, A_b, B_b, C_w, C_b);
    pack_blk<<<2048, 256>>>();
    cudaFuncSetAttribute(ss_main, cudaFuncAttributeMaxDynamicSharedMemorySize, SMEM_TOTAL);
    ss_main<<<128, 256, SMEM_TOTAL>>>(pre_x, pre_y, fwd_x, b_ih, b_hh, out);
}